// round 10
// baseline (speedup 1.0000x reference)
#include <cuda_runtime.h>
#include <cuda_fp16.h>

#define N       8192
#define GRID_A  148            // 1 block per SM, one wave
#define BLK_A   1024           // 32 warps, 8 cols/thread
#define NITER   10
#define LOG2E   1.4426950408889634f

// Multiplicative column scale d_j = exp(-c_j); row inverse sums rinv_i = 1/S_i.
__device__ float  g_d[N];
__device__ float  g_rinv[N];
__device__ float  g_part[(size_t)GRID_A * N];
// E_ij = exp(x_ij) stored as fp16, packed 8 per int4.
__device__ int4   g_E[(size_t)N * N / 8];

// ---------------------------------------------------------------------------
__global__ void init_d_kernel() {
    int i = blockIdx.x * blockDim.x + threadIdx.x;
    if (i < N) g_d[i] = 1.0f;
}

// ---------------------------------------------------------------------------
// decode 8 fp16 from an int4 into fp32
// ---------------------------------------------------------------------------
__device__ __forceinline__ void dec8h(const int4 q, float f[8]) {
    float2 a;
    a = __half22float2(*(const __half2*)&q.x); f[0] = a.x; f[1] = a.y;
    a = __half22float2(*(const __half2*)&q.y); f[2] = a.x; f[3] = a.y;
    a = __half22float2(*(const __half2*)&q.z); f[4] = a.x; f[5] = a.y;
    a = __half22float2(*(const __half2*)&q.w); f[6] = a.x; f[7] = a.y;
}

__device__ __forceinline__ int packh2(float a, float b) {
    __half2 h = __floats2half2_rn(a, b);
    return *(const int*)&h;
}

// ---------------------------------------------------------------------------
// Iteration 0 fused with E-precompute: d == 1. Read fp32 X, write E=exp(x)
// as fp16, and do iter-0's row pass (e computed FROM the rounded fp16 so all
// later iterations are self-consistent).
// ---------------------------------------------------------------------------
__global__ void __launch_bounds__(BLK_A, 1)
row_pass_first_kernel(const float* __restrict__ X) {
    __shared__ float s_warp[2][32];

    const int tid  = threadIdx.x;
    const int lane = tid & 31;
    const int wid  = tid >> 5;
    const int b    = blockIdx.x;
    const int row0 = (int)(((long long)N * b)       / GRID_A);
    const int row1 = (int)(((long long)N * (b + 1)) / GRID_A);

    float acc[8];
#pragma unroll
    for (int k = 0; k < 8; k++) acc[k] = 0.0f;

    const float4* x4 = (const float4*)X;
    // preload first row (8 fp32 = 2 float4 per thread)
    float4 xc[2];
    {
        const size_t rb = (size_t)row0 * 2048;
        xc[0] = __ldg(x4 + rb + 2 * tid);
        xc[1] = __ldg(x4 + rb + 2 * tid + 1);
    }

    int buf = 0;
    for (int row = row0; row < row1; ++row, buf ^= 1) {
        // prefetch next row
        float4 xn[2];
        {
            const int nr = (row + 1 < row1) ? row + 1 : row;
            const size_t rb = (size_t)nr * 2048;
            xn[0] = __ldg(x4 + rb + 2 * tid);
            xn[1] = __ldg(x4 + rb + 2 * tid + 1);
        }

        // E = exp(x) -> fp16; e = fp32(E16); row partial sum
        const float* xf = (const float*)xc;
        float E32[8];
#pragma unroll
        for (int k = 0; k < 8; k++) E32[k] = exp2f(xf[k] * LOG2E);

        int4 o;
        o.x = packh2(E32[0], E32[1]);
        o.y = packh2(E32[2], E32[3]);
        o.z = packh2(E32[4], E32[5]);
        o.w = packh2(E32[6], E32[7]);
        g_E[(size_t)row * 1024 + tid] = o;

        float e[8];
        dec8h(o, e);   // rounded values, consistent with later iterations
        float psum = ((e[0] + e[1]) + (e[2] + e[3])) + ((e[4] + e[5]) + (e[6] + e[7]));

        // warp reduce
#pragma unroll
        for (int off = 16; off > 0; off >>= 1)
            psum += __shfl_xor_sync(0xffffffffu, psum, off);
        if (lane == 0) s_warp[buf][wid] = psum;
        __syncthreads();

        float v = s_warp[buf][lane];
#pragma unroll
        for (int off = 16; off > 0; off >>= 1)
            v += __shfl_xor_sync(0xffffffffu, v, off);

        const float rcp = __fdividef(1.0f, v);
        if (tid == 0) g_rinv[row] = rcp;

#pragma unroll
        for (int k = 0; k < 8; k++) acc[k] = fmaf(e[k], rcp, acc[k]);

        xc[0] = xn[0]; xc[1] = xn[1];
    }

    float4* pp = (float4*)(g_part + (size_t)b * N);
    pp[2 * tid]     = make_float4(acc[0], acc[1], acc[2], acc[3]);
    pp[2 * tid + 1] = make_float4(acc[4], acc[5], acc[6], acc[7]);
}

// ---------------------------------------------------------------------------
// Steady-state row pass (iters 1..9): NO transcendentals.
//   e_ij = E_ij * d_j ;  S_i = sum_j e ;  rinv_i = 1/S_i ;  part += e * rinv
// 1024 threads x 8 cols/thread = one int4 (8 fp16) load per thread per row.
// ---------------------------------------------------------------------------
__global__ void __launch_bounds__(BLK_A, 1)
row_pass_kernel() {
    __shared__ float s_warp[2][32];

    const int tid  = threadIdx.x;
    const int lane = tid & 31;
    const int wid  = tid >> 5;
    const int b    = blockIdx.x;
    const int row0 = (int)(((long long)N * b)       / GRID_A);
    const int row1 = (int)(((long long)N * (b + 1)) / GRID_A);

    // column scales d_j for this thread's 8 columns (registers)
    float d[8];
    {
        const float4* d4 = (const float4*)g_d;
        float4 d0 = __ldg(d4 + 2 * tid);
        float4 d1 = __ldg(d4 + 2 * tid + 1);
        d[0]=d0.x; d[1]=d0.y; d[2]=d0.z; d[3]=d0.w;
        d[4]=d1.x; d[5]=d1.y; d[6]=d1.z; d[7]=d1.w;
    }

    float acc[8];
#pragma unroll
    for (int k = 0; k < 8; k++) acc[k] = 0.0f;

    // 2-deep row prefetch (one int4 per thread per row)
    int4 q0 = __ldg(&g_E[(size_t)row0 * 1024 + tid]);
    int4 q1 = __ldg(&g_E[(size_t)min(row0 + 1, row1 - 1) * 1024 + tid]);

    int buf = 0;
    for (int row = row0; row < row1; ++row, buf ^= 1) {
        // prefetch row+2
        const int pr = (row + 2 < row1) ? row + 2 : row1 - 1;
        int4 qn = __ldg(&g_E[(size_t)pr * 1024 + tid]);

        // e = E * d, row partial sum
        float f[8];
        dec8h(q0, f);
        float e[8];
#pragma unroll
        for (int k = 0; k < 8; k++) e[k] = f[k] * d[k];
        float psum = ((e[0] + e[1]) + (e[2] + e[3])) + ((e[4] + e[5]) + (e[6] + e[7]));

        // warp reduce
#pragma unroll
        for (int off = 16; off > 0; off >>= 1)
            psum += __shfl_xor_sync(0xffffffffu, psum, off);
        if (lane == 0) s_warp[buf][wid] = psum;
        __syncthreads();

        // second level: every warp reduces all 32 partials (no 2nd barrier)
        float v = s_warp[buf][lane];
#pragma unroll
        for (int off = 16; off > 0; off >>= 1)
            v += __shfl_xor_sync(0xffffffffu, v, off);

        const float rcp = __fdividef(1.0f, v);
        if (tid == 0) g_rinv[row] = rcp;

#pragma unroll
        for (int k = 0; k < 8; k++) acc[k] = fmaf(e[k], rcp, acc[k]);

        q0 = q1; q1 = qn;
    }

    float4* pp = (float4*)(g_part + (size_t)b * N);
    pp[2 * tid]     = make_float4(acc[0], acc[1], acc[2], acc[3]);
    pp[2 * tid + 1] = make_float4(acc[4], acc[5], acc[6], acc[7]);
}

// ---------------------------------------------------------------------------
// Column reduce: t_j = sum_b part[b][j];  d_j /= t_j   (no logs needed)
// 256 blocks x 256 threads: 32 cols x 8 p-groups, coalesced, 4-way MLP.
// ---------------------------------------------------------------------------
__global__ void __launch_bounds__(256)
col_reduce_kernel() {
    __shared__ float s[8][32];
    const int jl = threadIdx.x & 31;
    const int pg = threadIdx.x >> 5;
    const int j  = blockIdx.x * 32 + jl;

    const int b0 = (GRID_A * pg)       / 8;
    const int b1 = (GRID_A * (pg + 1)) / 8;

    const float* base = g_part + j;
    float a0 = 0.f, a1 = 0.f, a2 = 0.f, a3 = 0.f;
    int u = b0;
    for (; u + 4 <= b1; u += 4) {
        a0 += base[(size_t)(u + 0) * N];
        a1 += base[(size_t)(u + 1) * N];
        a2 += base[(size_t)(u + 2) * N];
        a3 += base[(size_t)(u + 3) * N];
    }
    for (; u < b1; ++u) a0 += base[(size_t)u * N];
    s[pg][jl] = (a0 + a1) + (a2 + a3);
    __syncthreads();

    if (pg == 0) {
        float t = 0.0f;
#pragma unroll
        for (int q = 0; q < 8; q++) t += s[q][jl];
        g_d[j] = __fdividef(g_d[j], t);
    }
}

// ---------------------------------------------------------------------------
// Final: out[i,j] = E_ij * d_j * rinv_i  (pure multiplies)
// ---------------------------------------------------------------------------
__global__ void __launch_bounds__(256)
final_kernel(float* __restrict__ out) {
    const size_t idx = (size_t)blockIdx.x * blockDim.x + threadIdx.x; // int4 idx
    const int    row = (int)(idx >> 10);        // 1024 int4 per row
    const int    cg  = (int)(idx & 1023);

    const float ri = __ldg(g_rinv + row);
    const float4* d4 = (const float4*)g_d;
    float4 d0 = __ldg(d4 + 2 * cg);
    float4 d1 = __ldg(d4 + 2 * cg + 1);

    int4 q = __ldg(&g_E[idx]);
    float f[8];
    dec8h(q, f);

    float4 o0, o1;
    o0.x = f[0] * (d0.x * ri);
    o0.y = f[1] * (d0.y * ri);
    o0.z = f[2] * (d0.z * ri);
    o0.w = f[3] * (d0.w * ri);
    o1.x = f[4] * (d1.x * ri);
    o1.y = f[5] * (d1.y * ri);
    o1.z = f[6] * (d1.z * ri);
    o1.w = f[7] * (d1.w * ri);

    float4* o4 = (float4*)out;
    o4[2 * idx]     = o0;
    o4[2 * idx + 1] = o1;
}

// ---------------------------------------------------------------------------
extern "C" void kernel_launch(void* const* d_in, const int* in_sizes, int n_in,
                              void* d_out, int out_size) {
    const float* X   = (const float*)d_in[0];
    float*       out = (float*)d_out;
    (void)in_sizes; (void)n_in; (void)out_size;

    init_d_kernel<<<N / 256, 256>>>();
    row_pass_first_kernel<<<GRID_A, BLK_A>>>(X);   // iter 0 + E precompute
    col_reduce_kernel<<<N / 32, 256>>>();
    for (int it = 1; it < NITER; ++it) {
        row_pass_kernel<<<GRID_A, BLK_A>>>();
        col_reduce_kernel<<<N / 32, 256>>>();
    }
    final_kernel<<<(size_t)N * N / 8 / 256, 256>>>(out);
}

// round 11
// speedup vs baseline: 1.0030x; 1.0030x over previous
#include <cuda_runtime.h>
#include <cuda_fp16.h>

#define N       8192
#define GRID_A  148            // 1 block per SM, one wave
#define BLK_A   1024           // 32 warps, 8 cols/thread
#define NITER   10
#define LOG2E   1.4426950408889634f

// Multiplicative column scale d_j = exp(-c_j); row inverse sums rinv_i = 1/S_i.
__device__ float  g_d[N];
__device__ float  g_rinv[N];
__device__ float  g_part[(size_t)GRID_A * N];
// E_ij = exp(x_ij) stored as fp16, packed 8 per int4.
__device__ int4   g_E[(size_t)N * N / 8];

// ---------------------------------------------------------------------------
__global__ void init_d_kernel() {
    int i = blockIdx.x * blockDim.x + threadIdx.x;
    if (i < N) g_d[i] = 1.0f;
}

// ---------------------------------------------------------------------------
// decode 8 fp16 from an int4 into fp32
// ---------------------------------------------------------------------------
__device__ __forceinline__ void dec8h(const int4 q, float f[8]) {
    float2 a;
    a = __half22float2(*(const __half2*)&q.x); f[0] = a.x; f[1] = a.y;
    a = __half22float2(*(const __half2*)&q.y); f[2] = a.x; f[3] = a.y;
    a = __half22float2(*(const __half2*)&q.z); f[4] = a.x; f[5] = a.y;
    a = __half22float2(*(const __half2*)&q.w); f[6] = a.x; f[7] = a.y;
}

__device__ __forceinline__ int packh2(float a, float b) {
    __half2 h = __floats2half2_rn(a, b);
    return *(const int*)&h;
}

// ---------------------------------------------------------------------------
// Iteration 0 fused with E-precompute: d == 1. Read fp32 X, write E=exp(x)
// as fp16, and do iter-0's row pass (e computed FROM the rounded fp16 so all
// later iterations are self-consistent).
// ---------------------------------------------------------------------------
__global__ void __launch_bounds__(BLK_A, 1)
row_pass_first_kernel(const float* __restrict__ X) {
    __shared__ float s_warp[2][32];

    const int tid  = threadIdx.x;
    const int lane = tid & 31;
    const int wid  = tid >> 5;
    const int b    = blockIdx.x;
    const int row0 = (int)(((long long)N * b)       / GRID_A);
    const int row1 = (int)(((long long)N * (b + 1)) / GRID_A);

    float acc[8];
#pragma unroll
    for (int k = 0; k < 8; k++) acc[k] = 0.0f;

    const float4* x4 = (const float4*)X;
    // preload first row (8 fp32 = 2 float4 per thread)
    float4 xc[2];
    {
        const size_t rb = (size_t)row0 * 2048;
        xc[0] = __ldg(x4 + rb + 2 * tid);
        xc[1] = __ldg(x4 + rb + 2 * tid + 1);
    }

    int buf = 0;
    for (int row = row0; row < row1; ++row, buf ^= 1) {
        // prefetch next row
        float4 xn[2];
        {
            const int nr = (row + 1 < row1) ? row + 1 : row;
            const size_t rb = (size_t)nr * 2048;
            xn[0] = __ldg(x4 + rb + 2 * tid);
            xn[1] = __ldg(x4 + rb + 2 * tid + 1);
        }

        // E = exp(x) -> fp16; e = fp32(E16); row partial sum
        const float* xf = (const float*)xc;
        float E32[8];
#pragma unroll
        for (int k = 0; k < 8; k++) E32[k] = exp2f(xf[k] * LOG2E);

        int4 o;
        o.x = packh2(E32[0], E32[1]);
        o.y = packh2(E32[2], E32[3]);
        o.z = packh2(E32[4], E32[5]);
        o.w = packh2(E32[6], E32[7]);
        g_E[(size_t)row * 1024 + tid] = o;

        float e[8];
        dec8h(o, e);   // rounded values, consistent with later iterations
        float psum = ((e[0] + e[1]) + (e[2] + e[3])) + ((e[4] + e[5]) + (e[6] + e[7]));

        // warp reduce
#pragma unroll
        for (int off = 16; off > 0; off >>= 1)
            psum += __shfl_xor_sync(0xffffffffu, psum, off);
        if (lane == 0) s_warp[buf][wid] = psum;
        __syncthreads();

        float v = s_warp[buf][lane];
#pragma unroll
        for (int off = 16; off > 0; off >>= 1)
            v += __shfl_xor_sync(0xffffffffu, v, off);

        const float rcp = __fdividef(1.0f, v);
        if (tid == 0) g_rinv[row] = rcp;

#pragma unroll
        for (int k = 0; k < 8; k++) acc[k] = fmaf(e[k], rcp, acc[k]);

        xc[0] = xn[0]; xc[1] = xn[1];
    }

    float4* pp = (float4*)(g_part + (size_t)b * N);
    pp[2 * tid]     = make_float4(acc[0], acc[1], acc[2], acc[3]);
    pp[2 * tid + 1] = make_float4(acc[4], acc[5], acc[6], acc[7]);
}

// ---------------------------------------------------------------------------
// Steady-state row pass (iters 1..9): NO transcendentals.
//   e_ij = E_ij * d_j ;  S_i = sum_j e ;  rinv_i = 1/S_i ;  part += e * rinv
// 1024 threads x 8 cols/thread = one int4 (8 fp16) load per thread per row.
// ---------------------------------------------------------------------------
__global__ void __launch_bounds__(BLK_A, 1)
row_pass_kernel() {
    __shared__ float s_warp[2][32];

    const int tid  = threadIdx.x;
    const int lane = tid & 31;
    const int wid  = tid >> 5;
    const int b    = blockIdx.x;
    const int row0 = (int)(((long long)N * b)       / GRID_A);
    const int row1 = (int)(((long long)N * (b + 1)) / GRID_A);

    // column scales d_j for this thread's 8 columns (registers)
    float d[8];
    {
        const float4* d4 = (const float4*)g_d;
        float4 d0 = __ldg(d4 + 2 * tid);
        float4 d1 = __ldg(d4 + 2 * tid + 1);
        d[0]=d0.x; d[1]=d0.y; d[2]=d0.z; d[3]=d0.w;
        d[4]=d1.x; d[5]=d1.y; d[6]=d1.z; d[7]=d1.w;
    }

    float acc[8];
#pragma unroll
    for (int k = 0; k < 8; k++) acc[k] = 0.0f;

    // 2-deep row prefetch (one int4 per thread per row)
    int4 q0 = __ldg(&g_E[(size_t)row0 * 1024 + tid]);
    int4 q1 = __ldg(&g_E[(size_t)min(row0 + 1, row1 - 1) * 1024 + tid]);

    int buf = 0;
    for (int row = row0; row < row1; ++row, buf ^= 1) {
        // prefetch row+2
        const int pr = (row + 2 < row1) ? row + 2 : row1 - 1;
        int4 qn = __ldg(&g_E[(size_t)pr * 1024 + tid]);

        // e = E * d, row partial sum
        float f[8];
        dec8h(q0, f);
        float e[8];
#pragma unroll
        for (int k = 0; k < 8; k++) e[k] = f[k] * d[k];
        float psum = ((e[0] + e[1]) + (e[2] + e[3])) + ((e[4] + e[5]) + (e[6] + e[7]));

        // warp reduce
#pragma unroll
        for (int off = 16; off > 0; off >>= 1)
            psum += __shfl_xor_sync(0xffffffffu, psum, off);
        if (lane == 0) s_warp[buf][wid] = psum;
        __syncthreads();

        // second level: every warp reduces all 32 partials (no 2nd barrier)
        float v = s_warp[buf][lane];
#pragma unroll
        for (int off = 16; off > 0; off >>= 1)
            v += __shfl_xor_sync(0xffffffffu, v, off);

        const float rcp = __fdividef(1.0f, v);
        if (tid == 0) g_rinv[row] = rcp;

#pragma unroll
        for (int k = 0; k < 8; k++) acc[k] = fmaf(e[k], rcp, acc[k]);

        q0 = q1; q1 = qn;
    }

    float4* pp = (float4*)(g_part + (size_t)b * N);
    pp[2 * tid]     = make_float4(acc[0], acc[1], acc[2], acc[3]);
    pp[2 * tid + 1] = make_float4(acc[4], acc[5], acc[6], acc[7]);
}

// ---------------------------------------------------------------------------
// Column reduce: t_j = sum_b part[b][j];  d_j /= t_j   (no logs needed)
// 256 blocks x 256 threads: 32 cols x 8 p-groups, coalesced, 4-way MLP.
// ---------------------------------------------------------------------------
__global__ void __launch_bounds__(256)
col_reduce_kernel() {
    __shared__ float s[8][32];
    const int jl = threadIdx.x & 31;
    const int pg = threadIdx.x >> 5;
    const int j  = blockIdx.x * 32 + jl;

    const int b0 = (GRID_A * pg)       / 8;
    const int b1 = (GRID_A * (pg + 1)) / 8;

    const float* base = g_part + j;
    float a0 = 0.f, a1 = 0.f, a2 = 0.f, a3 = 0.f;
    int u = b0;
    for (; u + 4 <= b1; u += 4) {
        a0 += base[(size_t)(u + 0) * N];
        a1 += base[(size_t)(u + 1) * N];
        a2 += base[(size_t)(u + 2) * N];
        a3 += base[(size_t)(u + 3) * N];
    }
    for (; u < b1; ++u) a0 += base[(size_t)u * N];
    s[pg][jl] = (a0 + a1) + (a2 + a3);
    __syncthreads();

    if (pg == 0) {
        float t = 0.0f;
#pragma unroll
        for (int q = 0; q < 8; q++) t += s[q][jl];
        g_d[j] = __fdividef(g_d[j], t);
    }
}

// ---------------------------------------------------------------------------
// Final: out[i,j] = E_ij * d_j * rinv_i  (pure multiplies)
// ---------------------------------------------------------------------------
__global__ void __launch_bounds__(256)
final_kernel(float* __restrict__ out) {
    const size_t idx = (size_t)blockIdx.x * blockDim.x + threadIdx.x; // int4 idx
    const int    row = (int)(idx >> 10);        // 1024 int4 per row
    const int    cg  = (int)(idx & 1023);

    const float ri = __ldg(g_rinv + row);
    const float4* d4 = (const float4*)g_d;
    float4 d0 = __ldg(d4 + 2 * cg);
    float4 d1 = __ldg(d4 + 2 * cg + 1);

    int4 q = __ldg(&g_E[idx]);
    float f[8];
    dec8h(q, f);

    float4 o0, o1;
    o0.x = f[0] * (d0.x * ri);
    o0.y = f[1] * (d0.y * ri);
    o0.z = f[2] * (d0.z * ri);
    o0.w = f[3] * (d0.w * ri);
    o1.x = f[4] * (d1.x * ri);
    o1.y = f[5] * (d1.y * ri);
    o1.z = f[6] * (d1.z * ri);
    o1.w = f[7] * (d1.w * ri);

    float4* o4 = (float4*)out;
    o4[2 * idx]     = o0;
    o4[2 * idx + 1] = o1;
}

// ---------------------------------------------------------------------------
extern "C" void kernel_launch(void* const* d_in, const int* in_sizes, int n_in,
                              void* d_out, int out_size) {
    const float* X   = (const float*)d_in[0];
    float*       out = (float*)d_out;
    (void)in_sizes; (void)n_in; (void)out_size;

    init_d_kernel<<<N / 256, 256>>>();
    row_pass_first_kernel<<<GRID_A, BLK_A>>>(X);   // iter 0 + E precompute
    col_reduce_kernel<<<N / 32, 256>>>();
    for (int it = 1; it < NITER; ++it) {
        row_pass_kernel<<<GRID_A, BLK_A>>>();
        col_reduce_kernel<<<N / 32, 256>>>();
    }
    final_kernel<<<(size_t)N * N / 8 / 256, 256>>>(out);
}

// round 12
// speedup vs baseline: 1.1354x; 1.1320x over previous
#include <cuda_runtime.h>
#include <cuda_fp16.h>

#define N       8192
#define GRID_A  148            // 1 block per SM, one wave
#define BLK_A   1024           // 32 warps, 8 cols/thread
#define NITER   10
#define NPAIR   (N / 2)        // 4096 row pairs
#define LOG2E   1.4426950408889634f
#define RS      256.0f         // rcp scale (keeps half rcp out of subnormals)
#define RSI     0.00390625f    // 1/256

// Multiplicative column scale d_j = exp(-c_j); row inverse sums rinv_i = 1/S_i.
__device__ float  g_d[N];
__device__ float  g_rinv[N];
__device__ float  g_part[(size_t)GRID_A * N];
// E_ij = exp(x_ij) stored as fp16, packed 8 per int4.
__device__ int4   g_E[(size_t)N * N / 8];

// ---------------------------------------------------------------------------
__global__ void init_d_kernel() {
    int i = blockIdx.x * blockDim.x + threadIdx.x;
    if (i < N) g_d[i] = 1.0f;
}

// ---------------------------------------------------------------------------
__device__ __forceinline__ __half2 bc_h2(int v) {         // bit-cast int -> half2
    return *reinterpret_cast<__half2*>(&v);
}

__device__ __forceinline__ void dec8h(const int4 q, float f[8]) {
    float2 a;
    a = __half22float2(bc_h2(q.x)); f[0] = a.x; f[1] = a.y;
    a = __half22float2(bc_h2(q.y)); f[2] = a.x; f[3] = a.y;
    a = __half22float2(bc_h2(q.z)); f[4] = a.x; f[5] = a.y;
    a = __half22float2(bc_h2(q.w)); f[6] = a.x; f[7] = a.y;
}

__device__ __forceinline__ int packh2(float a, float b) {
    __half2 h = __floats2half2_rn(a, b);
    return *(const int*)&h;
}

// ---------------------------------------------------------------------------
// Iteration 0 fused with E-precompute: d == 1. Read fp32 X, write E=exp(x)
// as fp16, and do iter-0's row pass (e computed FROM the rounded fp16).
// ---------------------------------------------------------------------------
__global__ void __launch_bounds__(BLK_A, 1)
row_pass_first_kernel(const float* __restrict__ X) {
    __shared__ float s_warp[2][32];

    const int tid  = threadIdx.x;
    const int lane = tid & 31;
    const int wid  = tid >> 5;
    const int b    = blockIdx.x;
    const int row0 = (int)(((long long)N * b)       / GRID_A);
    const int row1 = (int)(((long long)N * (b + 1)) / GRID_A);

    float acc[8];
#pragma unroll
    for (int k = 0; k < 8; k++) acc[k] = 0.0f;

    const float4* x4 = (const float4*)X;
    float4 xc[2];
    {
        const size_t rb = (size_t)row0 * 2048;
        xc[0] = __ldg(x4 + rb + 2 * tid);
        xc[1] = __ldg(x4 + rb + 2 * tid + 1);
    }

    int buf = 0;
    for (int row = row0; row < row1; ++row, buf ^= 1) {
        float4 xn[2];
        {
            const int nr = (row + 1 < row1) ? row + 1 : row;
            const size_t rb = (size_t)nr * 2048;
            xn[0] = __ldg(x4 + rb + 2 * tid);
            xn[1] = __ldg(x4 + rb + 2 * tid + 1);
        }

        const float* xf = (const float*)xc;
        float E32[8];
#pragma unroll
        for (int k = 0; k < 8; k++) E32[k] = exp2f(xf[k] * LOG2E);

        int4 o;
        o.x = packh2(E32[0], E32[1]);
        o.y = packh2(E32[2], E32[3]);
        o.z = packh2(E32[4], E32[5]);
        o.w = packh2(E32[6], E32[7]);
        g_E[(size_t)row * 1024 + tid] = o;

        float e[8];
        dec8h(o, e);
        float psum = ((e[0] + e[1]) + (e[2] + e[3])) + ((e[4] + e[5]) + (e[6] + e[7]));

#pragma unroll
        for (int off = 16; off > 0; off >>= 1)
            psum += __shfl_xor_sync(0xffffffffu, psum, off);
        if (lane == 0) s_warp[buf][wid] = psum;
        __syncthreads();

        float v = s_warp[buf][lane];
#pragma unroll
        for (int off = 16; off > 0; off >>= 1)
            v += __shfl_xor_sync(0xffffffffu, v, off);

        const float rcp = __fdividef(1.0f, v);
        if (tid == 0) g_rinv[row] = rcp;

#pragma unroll
        for (int k = 0; k < 8; k++) acc[k] = fmaf(e[k], rcp, acc[k]);

        xc[0] = xn[0]; xc[1] = xn[1];
    }

    float4* pp = (float4*)(g_part + (size_t)b * N);
    pp[2 * tid]     = make_float4(acc[0], acc[1], acc[2], acc[3]);
    pp[2 * tid + 1] = make_float4(acc[4], acc[5], acc[6], acc[7]);
}

// ---------------------------------------------------------------------------
// Steady-state row pass (iters 1..9): 2 rows per step, half2 math.
//   S_i = sum_j E_ij*d_j   (half2 partials, fp32 cross-lane)
//   part_j = d_j * sum_i E_ij * rcp_i   (HFMA2 accum, scaled by 256)
// ---------------------------------------------------------------------------
__global__ void __launch_bounds__(BLK_A, 1)
row_pass_kernel() {
    __shared__ float s_sum[2][2][32];   // [buf][row-in-pair][warp]

    const int tid  = threadIdx.x;
    const int lane = tid & 31;
    const int wid  = tid >> 5;
    const int b    = blockIdx.x;
    const int p0   = (int)(((long long)NPAIR * b)       / GRID_A);
    const int p1   = (int)(((long long)NPAIR * (b + 1)) / GRID_A);

    // column scales d_j as half2 (exactly representable: col_reduce rounds them)
    __half2 dh[4];
    {
        const float4* d4 = (const float4*)g_d;
        float4 a = __ldg(d4 + 2 * tid);
        float4 c = __ldg(d4 + 2 * tid + 1);
        dh[0] = __floats2half2_rn(a.x, a.y);
        dh[1] = __floats2half2_rn(a.z, a.w);
        dh[2] = __floats2half2_rn(c.x, c.y);
        dh[3] = __floats2half2_rn(c.z, c.w);
    }

    float acc[8];
#pragma unroll
    for (int k = 0; k < 8; k++) acc[k] = 0.0f;

    int4 qc[2], qn[2];
    qc[0] = __ldg(&g_E[(size_t)(2 * p0)     * 1024 + tid]);
    qc[1] = __ldg(&g_E[(size_t)(2 * p0 + 1) * 1024 + tid]);

    int buf = 0;
    for (int p = p0; p < p1; ++p, buf ^= 1) {
        // prefetch next pair (in flight across the whole reduce)
        const int pn = (p + 1 < p1) ? p + 1 : p;
        qn[0] = __ldg(&g_E[(size_t)(2 * pn)     * 1024 + tid]);
        qn[1] = __ldg(&g_E[(size_t)(2 * pn + 1) * 1024 + tid]);

        // per-lane psum for both rows (half2 then fp32)
        float ps0, ps1;
        {
            __half2 t  = __hmul2(bc_h2(qc[0].x), dh[0]);
            t          = __hfma2(bc_h2(qc[0].y), dh[1], t);
            __half2 t2 = __hmul2(bc_h2(qc[0].z), dh[2]);
            t2         = __hfma2(bc_h2(qc[0].w), dh[3], t2);
            float2 tf  = __half22float2(__hadd2(t, t2));
            ps0 = tf.x + tf.y;
        }
        {
            __half2 t  = __hmul2(bc_h2(qc[1].x), dh[0]);
            t          = __hfma2(bc_h2(qc[1].y), dh[1], t);
            __half2 t2 = __hmul2(bc_h2(qc[1].z), dh[2]);
            t2         = __hfma2(bc_h2(qc[1].w), dh[3], t2);
            float2 tf  = __half22float2(__hadd2(t, t2));
            ps1 = tf.x + tf.y;
        }

        // two interleaved warp butterflies (independent -> latency overlaps)
#pragma unroll
        for (int off = 16; off > 0; off >>= 1) {
            ps0 += __shfl_xor_sync(0xffffffffu, ps0, off);
            ps1 += __shfl_xor_sync(0xffffffffu, ps1, off);
        }
        if (lane == 0) {
            s_sum[buf][0][wid] = ps0;
            s_sum[buf][1][wid] = ps1;
        }
        __syncthreads();

        // cross-warp reduce, both rows interleaved
        float v0 = s_sum[buf][0][lane];
        float v1 = s_sum[buf][1][lane];
#pragma unroll
        for (int off = 16; off > 0; off >>= 1) {
            v0 += __shfl_xor_sync(0xffffffffu, v0, off);
            v1 += __shfl_xor_sync(0xffffffffu, v1, off);
        }

        const float rs0 = __fdividef(RS, v0);   // 256/S
        const float rs1 = __fdividef(RS, v1);
        if (tid == 0) {
            g_rinv[2 * p]     = rs0 * RSI;
            g_rinv[2 * p + 1] = rs1 * RSI;
        }
        const __half2 rh0 = __float2half2_rn(rs0);
        const __half2 rh1 = __float2half2_rn(rs1);

        // column accumulation: HFMA2 pair, flush to fp32 with 1/256 descale
        {
            __half2 a0 = __hmul2(bc_h2(qc[0].x), rh0);
            __half2 a1 = __hmul2(bc_h2(qc[0].y), rh0);
            __half2 a2 = __hmul2(bc_h2(qc[0].z), rh0);
            __half2 a3 = __hmul2(bc_h2(qc[0].w), rh0);
            a0 = __hfma2(bc_h2(qc[1].x), rh1, a0);
            a1 = __hfma2(bc_h2(qc[1].y), rh1, a1);
            a2 = __hfma2(bc_h2(qc[1].z), rh1, a2);
            a3 = __hfma2(bc_h2(qc[1].w), rh1, a3);
            float2 f;
            f = __half22float2(a0); acc[0] = fmaf(f.x, RSI, acc[0]); acc[1] = fmaf(f.y, RSI, acc[1]);
            f = __half22float2(a1); acc[2] = fmaf(f.x, RSI, acc[2]); acc[3] = fmaf(f.y, RSI, acc[3]);
            f = __half22float2(a2); acc[4] = fmaf(f.x, RSI, acc[4]); acc[5] = fmaf(f.y, RSI, acc[5]);
            f = __half22float2(a3); acc[6] = fmaf(f.x, RSI, acc[6]); acc[7] = fmaf(f.y, RSI, acc[7]);
        }

        qc[0] = qn[0]; qc[1] = qn[1];
    }

    // part_j = acc_j * d_j  (fp32 d)
    {
        const float4* d4 = (const float4*)g_d;
        float4 a = __ldg(d4 + 2 * tid);
        float4 c = __ldg(d4 + 2 * tid + 1);
        float4* pp = (float4*)(g_part + (size_t)b * N);
        pp[2 * tid]     = make_float4(acc[0] * a.x, acc[1] * a.y, acc[2] * a.z, acc[3] * a.w);
        pp[2 * tid + 1] = make_float4(acc[4] * c.x, acc[5] * c.y, acc[6] * c.z, acc[7] * c.w);
    }
}

// ---------------------------------------------------------------------------
// Column reduce: t_j = sum_b part[b][j];  d_j /= t_j.
// round_d != 0: round d through fp16 so the half2 row pass sees exact values.
// ---------------------------------------------------------------------------
__global__ void __launch_bounds__(256)
col_reduce_kernel(int round_d) {
    __shared__ float s[8][32];
    const int jl = threadIdx.x & 31;
    const int pg = threadIdx.x >> 5;
    const int j  = blockIdx.x * 32 + jl;

    const int b0 = (GRID_A * pg)       / 8;
    const int b1 = (GRID_A * (pg + 1)) / 8;

    const float* base = g_part + j;
    float a0 = 0.f, a1 = 0.f, a2 = 0.f, a3 = 0.f;
    int u = b0;
    for (; u + 4 <= b1; u += 4) {
        a0 += base[(size_t)(u + 0) * N];
        a1 += base[(size_t)(u + 1) * N];
        a2 += base[(size_t)(u + 2) * N];
        a3 += base[(size_t)(u + 3) * N];
    }
    for (; u < b1; ++u) a0 += base[(size_t)u * N];
    s[pg][jl] = (a0 + a1) + (a2 + a3);
    __syncthreads();

    if (pg == 0) {
        float t = 0.0f;
#pragma unroll
        for (int q = 0; q < 8; q++) t += s[q][jl];
        float dn = __fdividef(g_d[j], t);
        if (round_d) dn = __half2float(__float2half_rn(dn));
        g_d[j] = dn;
    }
}

// ---------------------------------------------------------------------------
// Final: out[i,j] = E_ij * d_j * rinv_i  (pure multiplies, fp32)
// ---------------------------------------------------------------------------
__global__ void __launch_bounds__(256)
final_kernel(float* __restrict__ out) {
    const size_t idx = (size_t)blockIdx.x * blockDim.x + threadIdx.x; // int4 idx
    const int    row = (int)(idx >> 10);        // 1024 int4 per row
    const int    cg  = (int)(idx & 1023);

    const float ri = __ldg(g_rinv + row);
    const float4* d4 = (const float4*)g_d;
    float4 d0 = __ldg(d4 + 2 * cg);
    float4 d1 = __ldg(d4 + 2 * cg + 1);

    int4 q = __ldg(&g_E[idx]);
    float f[8];
    dec8h(q, f);

    float4 o0, o1;
    o0.x = f[0] * (d0.x * ri);
    o0.y = f[1] * (d0.y * ri);
    o0.z = f[2] * (d0.z * ri);
    o0.w = f[3] * (d0.w * ri);
    o1.x = f[4] * (d1.x * ri);
    o1.y = f[5] * (d1.y * ri);
    o1.z = f[6] * (d1.z * ri);
    o1.w = f[7] * (d1.w * ri);

    float4* o4 = (float4*)out;
    o4[2 * idx]     = o0;
    o4[2 * idx + 1] = o1;
}

// ---------------------------------------------------------------------------
extern "C" void kernel_launch(void* const* d_in, const int* in_sizes, int n_in,
                              void* d_out, int out_size) {
    const float* X   = (const float*)d_in[0];
    float*       out = (float*)d_out;
    (void)in_sizes; (void)n_in; (void)out_size;

    init_d_kernel<<<N / 256, 256>>>();
    row_pass_first_kernel<<<GRID_A, BLK_A>>>(X);   // iter 0 + E precompute
    col_reduce_kernel<<<N / 32, 256>>>(1);
    for (int it = 1; it < NITER; ++it) {
        row_pass_kernel<<<GRID_A, BLK_A>>>();
        col_reduce_kernel<<<N / 32, 256>>>(it < NITER - 1 ? 1 : 0);
    }
    final_kernel<<<(size_t)N * N / 8 / 256, 256>>>(out);
}

// round 13
// speedup vs baseline: 1.1357x; 1.0002x over previous
#include <cuda_runtime.h>
#include <cuda_fp16.h>

#define N       8192
#define GRID_A  148            // 1 block per SM, one wave
#define BLK_A   1024           // 32 warps, 8 cols/thread
#define NITER   10
#define NPAIR   (N / 2)        // 4096 row pairs
#define LOG2E   1.4426950408889634f
#define RS      256.0f         // rcp scale (keeps half rcp out of subnormals)
#define RSI     0.00390625f    // 1/256

// Multiplicative column scale d_j = exp(-c_j); row inverse sums rinv_i = 1/S_i.
__device__ float  g_d[N];
__device__ float  g_rinv[N];
__device__ float  g_part[(size_t)GRID_A * N];
// E_ij = exp(x_ij) stored as fp16, packed 8 per int4.
__device__ int4   g_E[(size_t)N * N / 8];

// ---------------------------------------------------------------------------
__global__ void init_d_kernel() {
    int i = blockIdx.x * blockDim.x + threadIdx.x;
    if (i < N) g_d[i] = 1.0f;
}

// ---------------------------------------------------------------------------
__device__ __forceinline__ __half2 bc_h2(int v) {         // bit-cast int -> half2
    return *reinterpret_cast<__half2*>(&v);
}

__device__ __forceinline__ void dec8h(const int4 q, float f[8]) {
    float2 a;
    a = __half22float2(bc_h2(q.x)); f[0] = a.x; f[1] = a.y;
    a = __half22float2(bc_h2(q.y)); f[2] = a.x; f[3] = a.y;
    a = __half22float2(bc_h2(q.z)); f[4] = a.x; f[5] = a.y;
    a = __half22float2(bc_h2(q.w)); f[6] = a.x; f[7] = a.y;
}

__device__ __forceinline__ int packh2(float a, float b) {
    __half2 h = __floats2half2_rn(a, b);
    return *(const int*)&h;
}

// ---------------------------------------------------------------------------
// Iteration 0 fused with E-precompute: d == 1. Read fp32 X, write E=exp(x)
// as fp16, and do iter-0's row pass (e computed FROM the rounded fp16).
// ---------------------------------------------------------------------------
__global__ void __launch_bounds__(BLK_A, 1)
row_pass_first_kernel(const float* __restrict__ X) {
    __shared__ float s_warp[2][32];

    const int tid  = threadIdx.x;
    const int lane = tid & 31;
    const int wid  = tid >> 5;
    const int b    = blockIdx.x;
    const int row0 = (int)(((long long)N * b)       / GRID_A);
    const int row1 = (int)(((long long)N * (b + 1)) / GRID_A);

    float acc[8];
#pragma unroll
    for (int k = 0; k < 8; k++) acc[k] = 0.0f;

    const float4* x4 = (const float4*)X;
    float4 xc[2];
    {
        const size_t rb = (size_t)row0 * 2048;
        xc[0] = __ldg(x4 + rb + 2 * tid);
        xc[1] = __ldg(x4 + rb + 2 * tid + 1);
    }

    int buf = 0;
    for (int row = row0; row < row1; ++row, buf ^= 1) {
        float4 xn[2];
        {
            const int nr = (row + 1 < row1) ? row + 1 : row;
            const size_t rb = (size_t)nr * 2048;
            xn[0] = __ldg(x4 + rb + 2 * tid);
            xn[1] = __ldg(x4 + rb + 2 * tid + 1);
        }

        const float* xf = (const float*)xc;
        float E32[8];
#pragma unroll
        for (int k = 0; k < 8; k++) E32[k] = exp2f(xf[k] * LOG2E);

        int4 o;
        o.x = packh2(E32[0], E32[1]);
        o.y = packh2(E32[2], E32[3]);
        o.z = packh2(E32[4], E32[5]);
        o.w = packh2(E32[6], E32[7]);
        g_E[(size_t)row * 1024 + tid] = o;

        float e[8];
        dec8h(o, e);
        float psum = ((e[0] + e[1]) + (e[2] + e[3])) + ((e[4] + e[5]) + (e[6] + e[7]));

#pragma unroll
        for (int off = 16; off > 0; off >>= 1)
            psum += __shfl_xor_sync(0xffffffffu, psum, off);
        if (lane == 0) s_warp[buf][wid] = psum;
        __syncthreads();

        float v = s_warp[buf][lane];
#pragma unroll
        for (int off = 16; off > 0; off >>= 1)
            v += __shfl_xor_sync(0xffffffffu, v, off);

        const float rcp = __fdividef(1.0f, v);
        if (tid == 0) g_rinv[row] = rcp;

#pragma unroll
        for (int k = 0; k < 8; k++) acc[k] = fmaf(e[k], rcp, acc[k]);

        xc[0] = xn[0]; xc[1] = xn[1];
    }

    float4* pp = (float4*)(g_part + (size_t)b * N);
    pp[2 * tid]     = make_float4(acc[0], acc[1], acc[2], acc[3]);
    pp[2 * tid + 1] = make_float4(acc[4], acc[5], acc[6], acc[7]);
}

// ---------------------------------------------------------------------------
// Steady-state row pass (iters 1..9): 2 rows per step, half2 math.
//   S_i = sum_j E_ij*d_j   (half2 partials, fp32 cross-lane)
//   part_j = d_j * sum_i E_ij * rcp_i   (HFMA2 accum, scaled by 256)
// ---------------------------------------------------------------------------
__global__ void __launch_bounds__(BLK_A, 1)
row_pass_kernel() {
    __shared__ float s_sum[2][2][32];   // [buf][row-in-pair][warp]

    const int tid  = threadIdx.x;
    const int lane = tid & 31;
    const int wid  = tid >> 5;
    const int b    = blockIdx.x;
    const int p0   = (int)(((long long)NPAIR * b)       / GRID_A);
    const int p1   = (int)(((long long)NPAIR * (b + 1)) / GRID_A);

    // column scales d_j as half2 (exactly representable: col_reduce rounds them)
    __half2 dh[4];
    {
        const float4* d4 = (const float4*)g_d;
        float4 a = __ldg(d4 + 2 * tid);
        float4 c = __ldg(d4 + 2 * tid + 1);
        dh[0] = __floats2half2_rn(a.x, a.y);
        dh[1] = __floats2half2_rn(a.z, a.w);
        dh[2] = __floats2half2_rn(c.x, c.y);
        dh[3] = __floats2half2_rn(c.z, c.w);
    }

    float acc[8];
#pragma unroll
    for (int k = 0; k < 8; k++) acc[k] = 0.0f;

    int4 qc[2], qn[2];
    qc[0] = __ldg(&g_E[(size_t)(2 * p0)     * 1024 + tid]);
    qc[1] = __ldg(&g_E[(size_t)(2 * p0 + 1) * 1024 + tid]);

    int buf = 0;
    for (int p = p0; p < p1; ++p, buf ^= 1) {
        // prefetch next pair (in flight across the whole reduce)
        const int pn = (p + 1 < p1) ? p + 1 : p;
        qn[0] = __ldg(&g_E[(size_t)(2 * pn)     * 1024 + tid]);
        qn[1] = __ldg(&g_E[(size_t)(2 * pn + 1) * 1024 + tid]);

        // per-lane psum for both rows (half2 then fp32)
        float ps0, ps1;
        {
            __half2 t  = __hmul2(bc_h2(qc[0].x), dh[0]);
            t          = __hfma2(bc_h2(qc[0].y), dh[1], t);
            __half2 t2 = __hmul2(bc_h2(qc[0].z), dh[2]);
            t2         = __hfma2(bc_h2(qc[0].w), dh[3], t2);
            float2 tf  = __half22float2(__hadd2(t, t2));
            ps0 = tf.x + tf.y;
        }
        {
            __half2 t  = __hmul2(bc_h2(qc[1].x), dh[0]);
            t          = __hfma2(bc_h2(qc[1].y), dh[1], t);
            __half2 t2 = __hmul2(bc_h2(qc[1].z), dh[2]);
            t2         = __hfma2(bc_h2(qc[1].w), dh[3], t2);
            float2 tf  = __half22float2(__hadd2(t, t2));
            ps1 = tf.x + tf.y;
        }

        // two interleaved warp butterflies (independent -> latency overlaps)
#pragma unroll
        for (int off = 16; off > 0; off >>= 1) {
            ps0 += __shfl_xor_sync(0xffffffffu, ps0, off);
            ps1 += __shfl_xor_sync(0xffffffffu, ps1, off);
        }
        if (lane == 0) {
            s_sum[buf][0][wid] = ps0;
            s_sum[buf][1][wid] = ps1;
        }
        __syncthreads();

        // cross-warp reduce, both rows interleaved
        float v0 = s_sum[buf][0][lane];
        float v1 = s_sum[buf][1][lane];
#pragma unroll
        for (int off = 16; off > 0; off >>= 1) {
            v0 += __shfl_xor_sync(0xffffffffu, v0, off);
            v1 += __shfl_xor_sync(0xffffffffu, v1, off);
        }

        const float rs0 = __fdividef(RS, v0);   // 256/S
        const float rs1 = __fdividef(RS, v1);
        if (tid == 0) {
            g_rinv[2 * p]     = rs0 * RSI;
            g_rinv[2 * p + 1] = rs1 * RSI;
        }
        const __half2 rh0 = __float2half2_rn(rs0);
        const __half2 rh1 = __float2half2_rn(rs1);

        // column accumulation: HFMA2 pair, flush to fp32 with 1/256 descale
        {
            __half2 a0 = __hmul2(bc_h2(qc[0].x), rh0);
            __half2 a1 = __hmul2(bc_h2(qc[0].y), rh0);
            __half2 a2 = __hmul2(bc_h2(qc[0].z), rh0);
            __half2 a3 = __hmul2(bc_h2(qc[0].w), rh0);
            a0 = __hfma2(bc_h2(qc[1].x), rh1, a0);
            a1 = __hfma2(bc_h2(qc[1].y), rh1, a1);
            a2 = __hfma2(bc_h2(qc[1].z), rh1, a2);
            a3 = __hfma2(bc_h2(qc[1].w), rh1, a3);
            float2 f;
            f = __half22float2(a0); acc[0] = fmaf(f.x, RSI, acc[0]); acc[1] = fmaf(f.y, RSI, acc[1]);
            f = __half22float2(a1); acc[2] = fmaf(f.x, RSI, acc[2]); acc[3] = fmaf(f.y, RSI, acc[3]);
            f = __half22float2(a2); acc[4] = fmaf(f.x, RSI, acc[4]); acc[5] = fmaf(f.y, RSI, acc[5]);
            f = __half22float2(a3); acc[6] = fmaf(f.x, RSI, acc[6]); acc[7] = fmaf(f.y, RSI, acc[7]);
        }

        qc[0] = qn[0]; qc[1] = qn[1];
    }

    // part_j = acc_j * d_j  (fp32 d)
    {
        const float4* d4 = (const float4*)g_d;
        float4 a = __ldg(d4 + 2 * tid);
        float4 c = __ldg(d4 + 2 * tid + 1);
        float4* pp = (float4*)(g_part + (size_t)b * N);
        pp[2 * tid]     = make_float4(acc[0] * a.x, acc[1] * a.y, acc[2] * a.z, acc[3] * a.w);
        pp[2 * tid + 1] = make_float4(acc[4] * c.x, acc[5] * c.y, acc[6] * c.z, acc[7] * c.w);
    }
}

// ---------------------------------------------------------------------------
// Column reduce: t_j = sum_b part[b][j];  d_j /= t_j.
// round_d != 0: round d through fp16 so the half2 row pass sees exact values.
// ---------------------------------------------------------------------------
__global__ void __launch_bounds__(256)
col_reduce_kernel(int round_d) {
    __shared__ float s[8][32];
    const int jl = threadIdx.x & 31;
    const int pg = threadIdx.x >> 5;
    const int j  = blockIdx.x * 32 + jl;

    const int b0 = (GRID_A * pg)       / 8;
    const int b1 = (GRID_A * (pg + 1)) / 8;

    const float* base = g_part + j;
    float a0 = 0.f, a1 = 0.f, a2 = 0.f, a3 = 0.f;
    int u = b0;
    for (; u + 4 <= b1; u += 4) {
        a0 += base[(size_t)(u + 0) * N];
        a1 += base[(size_t)(u + 1) * N];
        a2 += base[(size_t)(u + 2) * N];
        a3 += base[(size_t)(u + 3) * N];
    }
    for (; u < b1; ++u) a0 += base[(size_t)u * N];
    s[pg][jl] = (a0 + a1) + (a2 + a3);
    __syncthreads();

    if (pg == 0) {
        float t = 0.0f;
#pragma unroll
        for (int q = 0; q < 8; q++) t += s[q][jl];
        float dn = __fdividef(g_d[j], t);
        if (round_d) dn = __half2float(__float2half_rn(dn));
        g_d[j] = dn;
    }
}

// ---------------------------------------------------------------------------
// Final: out[i,j] = E_ij * d_j * rinv_i  (pure multiplies, fp32)
// ---------------------------------------------------------------------------
__global__ void __launch_bounds__(256)
final_kernel(float* __restrict__ out) {
    const size_t idx = (size_t)blockIdx.x * blockDim.x + threadIdx.x; // int4 idx
    const int    row = (int)(idx >> 10);        // 1024 int4 per row
    const int    cg  = (int)(idx & 1023);

    const float ri = __ldg(g_rinv + row);
    const float4* d4 = (const float4*)g_d;
    float4 d0 = __ldg(d4 + 2 * cg);
    float4 d1 = __ldg(d4 + 2 * cg + 1);

    int4 q = __ldg(&g_E[idx]);
    float f[8];
    dec8h(q, f);

    float4 o0, o1;
    o0.x = f[0] * (d0.x * ri);
    o0.y = f[1] * (d0.y * ri);
    o0.z = f[2] * (d0.z * ri);
    o0.w = f[3] * (d0.w * ri);
    o1.x = f[4] * (d1.x * ri);
    o1.y = f[5] * (d1.y * ri);
    o1.z = f[6] * (d1.z * ri);
    o1.w = f[7] * (d1.w * ri);

    float4* o4 = (float4*)out;
    o4[2 * idx]     = o0;
    o4[2 * idx + 1] = o1;
}

// ---------------------------------------------------------------------------
extern "C" void kernel_launch(void* const* d_in, const int* in_sizes, int n_in,
                              void* d_out, int out_size) {
    const float* X   = (const float*)d_in[0];
    float*       out = (float*)d_out;
    (void)in_sizes; (void)n_in; (void)out_size;

    init_d_kernel<<<N / 256, 256>>>();
    row_pass_first_kernel<<<GRID_A, BLK_A>>>(X);   // iter 0 + E precompute
    col_reduce_kernel<<<N / 32, 256>>>(1);
    for (int it = 1; it < NITER; ++it) {
        row_pass_kernel<<<GRID_A, BLK_A>>>();
        col_reduce_kernel<<<N / 32, 256>>>(it < NITER - 1 ? 1 : 0);
    }
    final_kernel<<<(size_t)N * N / 8 / 256, 256>>>(out);
}